// round 2
// baseline (speedup 1.0000x reference)
#include <cuda_runtime.h>
#include <math.h>

#define T_STEPS 30
#define BATCH   256
#define HID     1024
#define LAYERS  4
#define ZCOLS   (4 * HID)   // 4096

#define BM 64
#define BN 128
#define BK 16
#define TM 4
#define TN 8

// Scratch (allocation-free: __device__ globals)
__device__ float g_z[BATCH * ZCOLS];          // gate pre-activations for one cell step
__device__ float g_h[LAYERS * BATCH * HID];   // keras hidden per layer
__device__ float g_c[LAYERS * BATCH * HID];   // keras cell per layer

__global__ void init_state_kernel(float* __restrict__ h, float* __restrict__ c, int n) {
    int i = blockIdx.x * blockDim.x + threadIdx.x;
    if (i < n) { h[i] = 0.0f; c[i] = 0.0f; }
}

// Z[b,n] = bias[n] + sum_k A1[b,k]*B1[k,n] + sum_k A2[b,k]*B2[k,n]
// A1,A2: [256,1024] row-major.  B1,B2: [1024,4096] row-major.  Z: [256,4096].
__global__ __launch_bounds__(256) void lstm_gemm_kernel(
    const float* __restrict__ A1, const float* __restrict__ A2,
    const float* __restrict__ B1, const float* __restrict__ B2,
    const float* __restrict__ bias, float* __restrict__ Z)
{
    __shared__ float As[BK][BM];
    __shared__ float Bs[BK][BN];

    const int tid = threadIdx.x;
    const int blockRow = blockIdx.y * BM;   // over BATCH (256)
    const int blockCol = blockIdx.x * BN;   // over ZCOLS (4096)

    // A tile load map: 64 rows x 16 cols as float4 -> one float4 per thread
    const int a_row = tid >> 2;             // 0..63
    const int a_c4  = (tid & 3) * 4;        // 0,4,8,12

    const int ty = tid >> 4;                // 0..15 -> M
    const int tx = tid & 15;                // 0..15 -> N

    float acc[TM][TN];
    #pragma unroll
    for (int i = 0; i < TM; ++i)
        #pragma unroll
        for (int j = 0; j < TN; ++j) acc[i][j] = 0.0f;

    #pragma unroll 1
    for (int src = 0; src < 2; ++src) {
        const float* A  = src ? A2 : A1;
        const float* Bm = src ? B2 : B1;

        #pragma unroll 1
        for (int k0 = 0; k0 < HID; k0 += BK) {
            // Load A tile (transposed into As[k][m])
            float4 av = *reinterpret_cast<const float4*>(
                &A[(blockRow + a_row) * HID + k0 + a_c4]);
            As[a_c4 + 0][a_row] = av.x;
            As[a_c4 + 1][a_row] = av.y;
            As[a_c4 + 2][a_row] = av.z;
            As[a_c4 + 3][a_row] = av.w;

            // Load B tile: 16 rows x 128 cols = 512 float4s, 2 per thread
            #pragma unroll
            for (int r = 0; r < 2; ++r) {
                int idx = tid + r * 256;
                int row = idx >> 5;              // 0..15
                int col = (idx & 31) * 4;        // 0..124
                *reinterpret_cast<float4*>(&Bs[row][col]) =
                    *reinterpret_cast<const float4*>(
                        &Bm[(size_t)(k0 + row) * ZCOLS + blockCol + col]);
            }
            __syncthreads();

            #pragma unroll
            for (int k = 0; k < BK; ++k) {
                float4 ra  = *reinterpret_cast<const float4*>(&As[k][ty * TM]);
                float4 rb0 = *reinterpret_cast<const float4*>(&Bs[k][tx * TN]);
                float4 rb1 = *reinterpret_cast<const float4*>(&Bs[k][tx * TN + 4]);
                float a_[TM] = {ra.x, ra.y, ra.z, ra.w};
                float b_[TN] = {rb0.x, rb0.y, rb0.z, rb0.w, rb1.x, rb1.y, rb1.z, rb1.w};
                #pragma unroll
                for (int i = 0; i < TM; ++i)
                    #pragma unroll
                    for (int j = 0; j < TN; ++j)
                        acc[i][j] = fmaf(a_[i], b_[j], acc[i][j]);
            }
            __syncthreads();
        }
    }

    // Epilogue: add bias, write Z
    #pragma unroll
    for (int i = 0; i < TM; ++i) {
        int row = blockRow + ty * TM + i;
        #pragma unroll
        for (int j = 0; j < TN; ++j) {
            int col = blockCol + tx * TN + j;
            Z[(size_t)row * ZCOLS + col] = acc[i][j] + bias[col];
        }
    }
}

// Gate math. z layout per row: [i | f | g | o] each HID wide.
__global__ __launch_bounds__(256) void lstm_cell_kernel(
    const float* __restrict__ Z, float* __restrict__ c, float* __restrict__ h,
    float* __restrict__ out)
{
    int idx = blockIdx.x * blockDim.x + threadIdx.x;   // < BATCH*HID
    int b = idx >> 10;
    int u = idx & (HID - 1);
    const float* z = Z + (size_t)b * ZCOLS;

    float zi = z[u];
    float zf = z[u + HID];
    float zg = z[u + 2 * HID];
    float zo = z[u + 3 * HID];

    float ig = 1.0f / (1.0f + expf(-zi));
    float fg = 1.0f / (1.0f + expf(-zf));
    float gg = tanhf(zg);
    float og = 1.0f / (1.0f + expf(-zo));

    float cn = fg * c[idx] + ig * gg;
    float hn = og * tanhf(cn);

    c[idx] = cn;
    h[idx] = hn;
    if (out) out[idx] = cn;   // source feeds keras cell state onward; final output
}

extern "C" void kernel_launch(void* const* d_in, const int* in_sizes, int n_in,
                              void* d_out, int out_size)
{
    const float* inputs = (const float*)d_in[0];   // [T,B,H]
    const float* kernel = (const float*)d_in[1];   // [L,H,4H]
    const float* rec    = (const float*)d_in[2];   // [L,H,4H]
    const float* bias   = (const float*)d_in[3];   // [L,4H]
    float* out = (float*)d_out;                    // [B,H]

    float *z_ptr, *h_ptr, *c_ptr;
    cudaGetSymbolAddress((void**)&z_ptr, g_z);
    cudaGetSymbolAddress((void**)&h_ptr, g_h);
    cudaGetSymbolAddress((void**)&c_ptr, g_c);

    const int state_n = LAYERS * BATCH * HID;
    init_state_kernel<<<(state_n + 255) / 256, 256>>>(h_ptr, c_ptr, state_n);

    dim3 gemm_grid(ZCOLS / BN, BATCH / BM);   // 32 x 4 = 128 blocks
    const int cell_blocks = (BATCH * HID) / 256;

    for (int t = 0; t < T_STEPS; ++t) {
        for (int j = 0; j < LAYERS; ++j) {
            const float* A1 = (j == 0)
                ? inputs + (size_t)t * BATCH * HID
                : c_ptr + (size_t)(j - 1) * BATCH * HID;
            const float* A2 = h_ptr + (size_t)j * BATCH * HID;
            const float* B1 = kernel + (size_t)j * HID * ZCOLS;
            const float* B2 = rec    + (size_t)j * HID * ZCOLS;
            const float* bj = bias   + (size_t)j * ZCOLS;

            lstm_gemm_kernel<<<gemm_grid, 256>>>(A1, A2, B1, B2, bj, z_ptr);

            float* final_out = (t == T_STEPS - 1 && j == LAYERS - 1) ? out : nullptr;
            lstm_cell_kernel<<<cell_blocks, 256>>>(
                z_ptr, c_ptr + (size_t)j * BATCH * HID,
                h_ptr + (size_t)j * BATCH * HID, final_out);
        }
    }
}

// round 4
// speedup vs baseline: 3.5604x; 3.5604x over previous
#include <cuda_runtime.h>
#include <cuda_bf16.h>
#include <cstdint>

#define T_STEPS 30
#define BATCH   256
#define HID     1024
#define LAYERS  4
#define ZCOLS   4096
#define BH      (BATCH * HID)

#define STAGES   4
#define KC       32            // bf16 k-elements per smem stage
#define NCHUNK   192           // 6 (A,B) pairs * (1024/32)
#define STAGE_BYTES 12288      // A 64x32x2 (4KB) + B 128x32x2 (8KB)
#define SMEM_BYTES  (STAGES * STAGE_BYTES)

// ---------------- scratch (__device__ globals, allocation-free) ----------------
__device__ __nv_bfloat16 g_w[2][LAYERS][2][ZCOLS * HID]; // [kern/rec][layer][hi/lo][n'][k]
__device__ __nv_bfloat16 g_xh[T_STEPS * BH];
__device__ __nv_bfloat16 g_xl[T_STEPS * BH];
__device__ float         g_c[LAYERS][BH];
__device__ __nv_bfloat16 g_hh[LAYERS][2][BH];
__device__ __nv_bfloat16 g_hl[LAYERS][2][BH];
__device__ __nv_bfloat16 g_curh[2][BH];
__device__ __nv_bfloat16 g_curl[2][BH];
__device__ float         g_biasp[LAYERS][ZCOLS];

// ---------------- helpers ----------------
__device__ __forceinline__ uint32_t smem_u32(const void* p) {
    uint32_t a;
    asm("{ .reg .u64 t; cvta.to.shared.u64 t, %1; cvt.u32.u64 %0, t; }" : "=r"(a) : "l"(p));
    return a;
}
__device__ __forceinline__ void cp16(uint32_t dst, const void* src) {
    asm volatile("cp.async.cg.shared.global [%0], [%1], 16;"
                 :: "r"(dst), "l"(__cvta_generic_to_global(src)) : "memory");
}
__device__ __forceinline__ uint32_t sw64(uint32_t off) {
    return off ^ ((off >> 3) & 0x30);
}
__device__ __forceinline__ void ldmat4(uint32_t addr, uint32_t& r0, uint32_t& r1,
                                       uint32_t& r2, uint32_t& r3) {
    asm volatile("ldmatrix.sync.aligned.m8n8.x4.shared.b16 {%0,%1,%2,%3}, [%4];"
                 : "=r"(r0), "=r"(r1), "=r"(r2), "=r"(r3) : "r"(addr));
}
__device__ __forceinline__ void mma_bf16(float& d0, float& d1, float& d2, float& d3,
                                         uint32_t a0, uint32_t a1, uint32_t a2, uint32_t a3,
                                         uint32_t b0, uint32_t b1) {
    asm volatile("mma.sync.aligned.m16n8k16.row.col.f32.bf16.bf16.f32 "
                 "{%0,%1,%2,%3},{%4,%5,%6,%7},{%8,%9},{%0,%1,%2,%3};"
                 : "+f"(d0), "+f"(d1), "+f"(d2), "+f"(d3)
                 : "r"(a0), "r"(a1), "r"(a2), "r"(a3), "r"(b0), "r"(b1));
}
__device__ __forceinline__ void split_bf(float x, uint32_t& hi, uint32_t& lo) {
    __nv_bfloat16 h = __float2bfloat16(x);
    __nv_bfloat16 l = __float2bfloat16(x - __bfloat162float(h));
    hi = (uint32_t)__bfloat16_as_ushort(h);
    lo = (uint32_t)__bfloat16_as_ushort(l);
}

// ---------------- init kernels ----------------
__global__ void zero_state_kernel() {
    int i = blockIdx.x * blockDim.x + threadIdx.x;
    int nc = LAYERS * BH;
    int nh = LAYERS * 2 * BH / 2;
    if (i < nc) ((float*)g_c)[i] = 0.0f;
    if (i < nh) { ((uint32_t*)g_hh)[i] = 0u; ((uint32_t*)g_hl)[i] = 0u; }
}

__global__ void bias_perm_kernel(const float* __restrict__ bias) {
    int i = blockIdx.x * blockDim.x + threadIdx.x;
    if (i >= LAYERS * ZCOLS) return;
    int l = i >> 12, n = i & 4095;
    int np = 4 * (n & 1023) + (n >> 10);
    g_biasp[l][np] = bias[i];
}

// transpose [1024,4096] -> hi/lo bf16 [4096(gate-permuted)][1024]
__global__ void wsplit_kernel(const float* __restrict__ kern, const float* __restrict__ rec) {
    __shared__ float t[32][33];
    int mat = blockIdx.z >> 2;
    int l   = blockIdx.z & 3;
    const float* src = (mat ? rec : kern) + (size_t)l * HID * ZCOLS;
    int n0 = blockIdx.x * 32, k0 = blockIdx.y * 32;
    int tx = threadIdx.x, ty = threadIdx.y;
    #pragma unroll
    for (int i = 0; i < 4; i++)
        t[ty + i * 8][tx] = src[(size_t)(k0 + ty + i * 8) * ZCOLS + n0 + tx];
    __syncthreads();
    __nv_bfloat16* oh = g_w[mat][l][0];
    __nv_bfloat16* ol = g_w[mat][l][1];
    #pragma unroll
    for (int i = 0; i < 4; i++) {
        int nl = ty + i * 8;
        int n  = n0 + nl;
        int np = 4 * (n & 1023) + (n >> 10);
        float v = t[tx][nl];
        __nv_bfloat16 h = __float2bfloat16(v);
        oh[(size_t)np * HID + k0 + tx] = h;
        ol[(size_t)np * HID + k0 + tx] = __float2bfloat16(v - __bfloat162float(h));
    }
}

__global__ void xsplit_kernel(const float* __restrict__ x) {
    int i = blockIdx.x * blockDim.x + threadIdx.x;
    if (i >= T_STEPS * BH) return;
    float v = x[i];
    __nv_bfloat16 h = __float2bfloat16(v);
    g_xh[i] = h;
    g_xl[i] = __float2bfloat16(v - __bfloat162float(h));
}

// ---------------- fused LSTM step: bf16 mma.sync GEMM + gates ----------------
__global__ __launch_bounds__(256, 1) void lstm_step_kernel(
    const __nv_bfloat16* __restrict__ ah, const __nv_bfloat16* __restrict__ al,
    const __nv_bfloat16* __restrict__ hhp, const __nv_bfloat16* __restrict__ hlp,
    const __nv_bfloat16* __restrict__ w1h, const __nv_bfloat16* __restrict__ w1l,
    const __nv_bfloat16* __restrict__ w2h, const __nv_bfloat16* __restrict__ w2l,
    const float* __restrict__ biasp,
    float* __restrict__ cst,
    __nv_bfloat16* __restrict__ curh_o, __nv_bfloat16* __restrict__ curl_o,
    __nv_bfloat16* __restrict__ hh_o, __nv_bfloat16* __restrict__ hl_o,
    float* __restrict__ fout)
{
    extern __shared__ char smem[];
    const uint32_t sb = smem_u32(smem);
    const int tid  = threadIdx.x;
    const int lane = tid & 31;
    const int wid  = tid >> 5;
    const int wm = wid >> 2;           // 0..1  (rows)
    const int wn = wid & 3;            // 0..3  (cols)
    const int blockN   = blockIdx.x * 128;
    const int blockRow = blockIdx.y * 64;

    const __nv_bfloat16* Ap[6] = {ah, ah, al, hhp, hhp, hlp};
    const __nv_bfloat16* Bp[6] = {w1h, w1l, w1h, w2h, w2l, w2h};

    // per-thread load map (A: 1 cp16, B: 2 cp16)
    const int a_row = tid >> 2, a_c16 = tid & 3;
    const uint32_t aDst = sw64((uint32_t)(a_row * 64 + a_c16 * 16));
    const int b_row0 = tid >> 2, b_c16 = tid & 3;      // rows 0..63
    const int b_row1 = b_row0 + 64;                    // rows 64..127
    const uint32_t bDst0 = 4096u + sw64((uint32_t)(b_row0 * 64 + b_c16 * 16));
    const uint32_t bDst1 = 4096u + sw64((uint32_t)(b_row1 * 64 + b_c16 * 16));

    auto load_chunk = [&](int j, int s) {
        int p   = j >> 5;
        int kc0 = (j & 31) * KC;
        const __nv_bfloat16* As = Ap[p];
        const __nv_bfloat16* Bs = Bp[p];
        uint32_t base = sb + (uint32_t)s * STAGE_BYTES;
        cp16(base + aDst, As + (size_t)(blockRow + a_row) * HID + kc0 + a_c16 * 8);
        cp16(base + bDst0, Bs + (size_t)(blockN + b_row0) * HID + kc0 + b_c16 * 8);
        cp16(base + bDst1, Bs + (size_t)(blockN + b_row1) * HID + kc0 + b_c16 * 8);
    };

    // ldmatrix smem offsets (relative to stage base), per lane
    uint32_t aOff[2][2], bOff[2][2];
    {
        int mA  = wm * 32 + (lane & 7) + ((lane >> 3) & 1) * 8;
        int kA  = (lane >> 4) * 16;     // bytes
        int nB  = wn * 32 + (lane & 7) + ((lane >> 4) & 1) * 8;
        int kB  = ((lane >> 3) & 1) * 16;
        #pragma unroll
        for (int ks = 0; ks < 2; ks++) {
            #pragma unroll
            for (int mi = 0; mi < 2; mi++)
                aOff[mi][ks] = sw64((uint32_t)((mA + mi * 16) * 64 + ks * 32 + kA));
            #pragma unroll
            for (int nh2 = 0; nh2 < 2; nh2++)
                bOff[nh2][ks] = 4096u + sw64((uint32_t)((nB + nh2 * 16) * 64 + ks * 32 + kB));
        }
    }

    float d[2][4][4];
    #pragma unroll
    for (int mi = 0; mi < 2; mi++)
        #pragma unroll
        for (int ni = 0; ni < 4; ni++)
            #pragma unroll
            for (int r = 0; r < 4; r++) d[mi][ni][r] = 0.0f;

    // prologue: stages 0..2
    #pragma unroll
    for (int j = 0; j < STAGES - 1; j++) {
        load_chunk(j, j);
        asm volatile("cp.async.commit_group;" ::: "memory");
    }

    #pragma unroll 1
    for (int i = 0; i < NCHUNK; i++) {
        asm volatile("cp.async.wait_group %0;" :: "n"(STAGES - 2) : "memory");
        __syncthreads();
        // issue next loads (overwrites stage computed last iteration)
        int jn = i + STAGES - 1;
        if (jn < NCHUNK) load_chunk(jn, jn & (STAGES - 1));
        asm volatile("cp.async.commit_group;" ::: "memory");

        uint32_t base = sb + (uint32_t)(i & (STAGES - 1)) * STAGE_BYTES;
        #pragma unroll
        for (int ks = 0; ks < 2; ks++) {
            uint32_t a[2][4], bt[2][4];
            #pragma unroll
            for (int mi = 0; mi < 2; mi++)
                ldmat4(base + aOff[mi][ks], a[mi][0], a[mi][1], a[mi][2], a[mi][3]);
            #pragma unroll
            for (int nh2 = 0; nh2 < 2; nh2++)
                ldmat4(base + bOff[nh2][ks], bt[nh2][0], bt[nh2][1], bt[nh2][2], bt[nh2][3]);
            #pragma unroll
            for (int mi = 0; mi < 2; mi++)
                #pragma unroll
                for (int ni = 0; ni < 4; ni++)
                    mma_bf16(d[mi][ni][0], d[mi][ni][1], d[mi][ni][2], d[mi][ni][3],
                             a[mi][0], a[mi][1], a[mi][2], a[mi][3],
                             bt[ni >> 1][(ni & 1) * 2], bt[ni >> 1][(ni & 1) * 2 + 1]);
        }
    }

    __syncthreads();   // done with pipeline smem; reuse for epilogue staging

    // stage accumulators: per-warp region [32 rows][33 floats]
    float* st = (float*)(smem + (size_t)wid * 32 * 33 * 4);
    #pragma unroll
    for (int mi = 0; mi < 2; mi++) {
        int r0 = mi * 16 + (lane >> 2);
        #pragma unroll
        for (int ni = 0; ni < 4; ni++) {
            int c0 = ni * 8 + 2 * (lane & 3);
            st[r0 * 33 + c0]           = d[mi][ni][0];
            st[r0 * 33 + c0 + 1]       = d[mi][ni][1];
            st[(r0 + 8) * 33 + c0]     = d[mi][ni][2];
            st[(r0 + 8) * 33 + c0 + 1] = d[mi][ni][3];
        }
    }
    __syncwarp();

    // gate math: lane -> one batch row, 8 hidden units
    {
        const float* zrow = st + lane * 33;
        const int m  = blockRow + wm * 32 + lane;
        const int ug = (blockN >> 2) + wn * 8;          // unit base
        const float4* bq = (const float4*)(biasp + blockN + wn * 32);
        float* cp = cst + (size_t)m * HID + ug;
        float4 co0 = *(const float4*)(cp);
        float4 co1 = *(const float4*)(cp + 4);
        float cold[8] = {co0.x, co0.y, co0.z, co0.w, co1.x, co1.y, co1.z, co1.w};
        float cn[8], hn[8];
        #pragma unroll
        for (int k = 0; k < 8; k++) {
            float4 bb = bq[k];
            float zi = zrow[4 * k]     + bb.x;
            float zf = zrow[4 * k + 1] + bb.y;
            float zg = zrow[4 * k + 2] + bb.z;
            float zo = zrow[4 * k + 3] + bb.w;
            float ig = 1.0f / (1.0f + __expf(-zi));
            float fg = 1.0f / (1.0f + __expf(-zf));
            float gg = tanhf(zg);
            float og = 1.0f / (1.0f + __expf(-zo));
            float c_ = fg * cold[k] + ig * gg;
            cn[k] = c_;
            hn[k] = og * tanhf(c_);
        }
        *(float4*)(cp)     = make_float4(cn[0], cn[1], cn[2], cn[3]);
        *(float4*)(cp + 4) = make_float4(cn[4], cn[5], cn[6], cn[7]);

        uint32_t chi[8], clo[8], hhi[8], hlo[8];
        #pragma unroll
        for (int k = 0; k < 8; k++) {
            split_bf(cn[k], chi[k], clo[k]);
            split_bf(hn[k], hhi[k], hlo[k]);
        }
        size_t so = (size_t)m * HID + ug;
        uint4 v;
        v = make_uint4(chi[0] | (chi[1] << 16), chi[2] | (chi[3] << 16),
                       chi[4] | (chi[5] << 16), chi[6] | (chi[7] << 16));
        *(uint4*)(curh_o + so) = v;
        v = make_uint4(clo[0] | (clo[1] << 16), clo[2] | (clo[3] << 16),
                       clo[4] | (clo[5] << 16), clo[6] | (clo[7] << 16));
        *(uint4*)(curl_o + so) = v;
        v = make_uint4(hhi[0] | (hhi[1] << 16), hhi[2] | (hhi[3] << 16),
                       hhi[4] | (hhi[5] << 16), hhi[6] | (hhi[7] << 16));
        *(uint4*)(hh_o + so) = v;
        v = make_uint4(hlo[0] | (hlo[1] << 16), hlo[2] | (hlo[3] << 16),
                       hlo[4] | (hlo[5] << 16), hlo[6] | (hlo[7] << 16));
        *(uint4*)(hl_o + so) = v;

        if (fout) {
            *(float4*)(fout + so)     = make_float4(cn[0], cn[1], cn[2], cn[3]);
            *(float4*)(fout + so + 4) = make_float4(cn[4], cn[5], cn[6], cn[7]);
        }
    }
}

// ---------------- host launcher ----------------
extern "C" void kernel_launch(void* const* d_in, const int* in_sizes, int n_in,
                              void* d_out, int out_size)
{
    const float* inputs = (const float*)d_in[0];
    const float* kernel = (const float*)d_in[1];
    const float* rec    = (const float*)d_in[2];
    const float* bias   = (const float*)d_in[3];
    float* out = (float*)d_out;

    cudaFuncSetAttribute(lstm_step_kernel, cudaFuncAttributeMaxDynamicSharedMemorySize, SMEM_BYTES);

    __nv_bfloat16 *w_ptr, *xh_ptr, *xl_ptr, *hh_ptr, *hl_ptr, *curh_ptr, *curl_ptr;
    float *c_ptr, *biasp_ptr;
    cudaGetSymbolAddress((void**)&w_ptr, g_w);
    cudaGetSymbolAddress((void**)&xh_ptr, g_xh);
    cudaGetSymbolAddress((void**)&xl_ptr, g_xl);
    cudaGetSymbolAddress((void**)&hh_ptr, g_hh);
    cudaGetSymbolAddress((void**)&hl_ptr, g_hl);
    cudaGetSymbolAddress((void**)&curh_ptr, g_curh);
    cudaGetSymbolAddress((void**)&curl_ptr, g_curl);
    cudaGetSymbolAddress((void**)&c_ptr, g_c);
    cudaGetSymbolAddress((void**)&biasp_ptr, g_biasp);

    const size_t WSTRIDE = (size_t)ZCOLS * HID;

    {
        int n = LAYERS * BH;
        zero_state_kernel<<<(n + 255) / 256, 256>>>();
        bias_perm_kernel<<<(LAYERS * ZCOLS + 255) / 256, 256>>>(bias);
        wsplit_kernel<<<dim3(ZCOLS / 32, HID / 32, 2 * LAYERS), dim3(32, 8)>>>(kernel, rec);
        xsplit_kernel<<<(T_STEPS * BH + 255) / 256, 256>>>(inputs);
    }

    dim3 grid(32, 4);
    for (int t = 0; t < T_STEPS; t++) {
        for (int j = 0; j < LAYERS; j++) {
            const __nv_bfloat16* ah = (j == 0) ? xh_ptr + (size_t)t * BH : curh_ptr + (size_t)(j & 1) * BH;
            const __nv_bfloat16* al = (j == 0) ? xl_ptr + (size_t)t * BH : curl_ptr + (size_t)(j & 1) * BH;
            const __nv_bfloat16* hhp = hh_ptr + ((size_t)j * 2 + (t & 1)) * BH;
            const __nv_bfloat16* hlp = hl_ptr + ((size_t)j * 2 + (t & 1)) * BH;
            const __nv_bfloat16* w1h = w_ptr + ((size_t)(0 * LAYERS + j) * 2 + 0) * WSTRIDE;
            const __nv_bfloat16* w1l = w_ptr + ((size_t)(0 * LAYERS + j) * 2 + 1) * WSTRIDE;
            const __nv_bfloat16* w2h = w_ptr + ((size_t)(1 * LAYERS + j) * 2 + 0) * WSTRIDE;
            const __nv_bfloat16* w2l = w_ptr + ((size_t)(1 * LAYERS + j) * 2 + 1) * WSTRIDE;

            lstm_step_kernel<<<grid, 256, SMEM_BYTES>>>(
                ah, al, hhp, hlp, w1h, w1l, w2h, w2l,
                biasp_ptr + (size_t)j * ZCOLS,
                c_ptr + (size_t)j * BH,
                curh_ptr + (size_t)((j + 1) & 1) * BH,
                curl_ptr + (size_t)((j + 1) & 1) * BH,
                hh_ptr + ((size_t)j * 2 + ((t + 1) & 1)) * BH,
                hl_ptr + ((size_t)j * 2 + ((t + 1) & 1)) * BH,
                (t == T_STEPS - 1 && j == LAYERS - 1) ? out : nullptr);
        }
    }
}

// round 5
// speedup vs baseline: 3.7964x; 1.0663x over previous
#include <cuda_runtime.h>
#include <cuda_bf16.h>
#include <cstdint>

#define T_STEPS 30
#define BATCH   256
#define HID     1024
#define LAYERS  4
#define ZCOLS   4096
#define BH      (BATCH * HID)
#define NSTEPS  (T_STEPS * LAYERS)   // 120

#define STAGES      3
#define KC          64                // bf16 k-elements per smem stage
#define NCHUNK      96                // 6 (A,B) pairs * (1024/64)
#define A_BYTES     8192              // 64 x 64 x 2
#define B_BYTES     16384             // 128 x 64 x 2
#define STAGE_BYTES (A_BYTES + B_BYTES)          // 24576
#define SMEM_BYTES  (STAGES * STAGE_BYTES)       // 73728
#define GRID_CTAS   128

// ---------------- scratch (__device__ globals, allocation-free) ----------------
__device__ __nv_bfloat16 g_w[2][LAYERS][2][ZCOLS * HID]; // [kern/rec][layer][hi/lo][n'][k]
__device__ __nv_bfloat16 g_xh[T_STEPS * BH];
__device__ __nv_bfloat16 g_xl[T_STEPS * BH];
__device__ float         g_c[LAYERS][BH];
__device__ __nv_bfloat16 g_hh[LAYERS][2][BH];
__device__ __nv_bfloat16 g_hl[LAYERS][2][BH];
__device__ __nv_bfloat16 g_curh[2][BH];
__device__ __nv_bfloat16 g_curl[2][BH];
__device__ float         g_biasp[LAYERS][ZCOLS];
__device__ unsigned      g_bar;

// ---------------- helpers ----------------
__device__ __forceinline__ uint32_t smem_u32(const void* p) {
    uint32_t a;
    asm("{ .reg .u64 t; cvta.to.shared.u64 t, %1; cvt.u32.u64 %0, t; }" : "=r"(a) : "l"(p));
    return a;
}
__device__ __forceinline__ void cp16(uint32_t dst, const void* src) {
    asm volatile("cp.async.cg.shared.global [%0], [%1], 16;"
                 :: "r"(dst), "l"(__cvta_generic_to_global(src)) : "memory");
}
__device__ __forceinline__ uint32_t sw128(uint32_t off) {
    return off ^ ((off >> 3) & 0x70);
}
__device__ __forceinline__ void ldmat4(uint32_t addr, uint32_t& r0, uint32_t& r1,
                                       uint32_t& r2, uint32_t& r3) {
    asm volatile("ldmatrix.sync.aligned.m8n8.x4.shared.b16 {%0,%1,%2,%3}, [%4];"
                 : "=r"(r0), "=r"(r1), "=r"(r2), "=r"(r3) : "r"(addr));
}
__device__ __forceinline__ void mma_bf16(float& d0, float& d1, float& d2, float& d3,
                                         uint32_t a0, uint32_t a1, uint32_t a2, uint32_t a3,
                                         uint32_t b0, uint32_t b1) {
    asm volatile("mma.sync.aligned.m16n8k16.row.col.f32.bf16.bf16.f32 "
                 "{%0,%1,%2,%3},{%4,%5,%6,%7},{%8,%9},{%0,%1,%2,%3};"
                 : "+f"(d0), "+f"(d1), "+f"(d2), "+f"(d3)
                 : "r"(a0), "r"(a1), "r"(a2), "r"(a3), "r"(b0), "r"(b1));
}
__device__ __forceinline__ void split_bf(float x, uint32_t& hi, uint32_t& lo) {
    __nv_bfloat16 h = __float2bfloat16(x);
    __nv_bfloat16 l = __float2bfloat16(x - __bfloat162float(h));
    hi = (uint32_t)__bfloat16_as_ushort(h);
    lo = (uint32_t)__bfloat16_as_ushort(l);
}

// ---------------- init kernels ----------------
__global__ void zero_state_kernel() {
    int i = blockIdx.x * blockDim.x + threadIdx.x;
    if (i == 0) g_bar = 0u;
    int nc = LAYERS * BH;
    int nh = LAYERS * 2 * BH / 2;
    if (i < nc) ((float*)g_c)[i] = 0.0f;
    if (i < nh) { ((uint32_t*)g_hh)[i] = 0u; ((uint32_t*)g_hl)[i] = 0u; }
}

__global__ void bias_perm_kernel(const float* __restrict__ bias) {
    int i = blockIdx.x * blockDim.x + threadIdx.x;
    if (i >= LAYERS * ZCOLS) return;
    int l = i >> 12, n = i & 4095;
    int np = 4 * (n & 1023) + (n >> 10);
    g_biasp[l][np] = bias[i];
}

// transpose [1024,4096] -> hi/lo bf16 [4096(gate-permuted)][1024]
__global__ void wsplit_kernel(const float* __restrict__ kern, const float* __restrict__ rec) {
    __shared__ float t[32][33];
    int mat = blockIdx.z >> 2;
    int l   = blockIdx.z & 3;
    const float* src = (mat ? rec : kern) + (size_t)l * HID * ZCOLS;
    int n0 = blockIdx.x * 32, k0 = blockIdx.y * 32;
    int tx = threadIdx.x, ty = threadIdx.y;
    #pragma unroll
    for (int i = 0; i < 4; i++)
        t[ty + i * 8][tx] = src[(size_t)(k0 + ty + i * 8) * ZCOLS + n0 + tx];
    __syncthreads();
    __nv_bfloat16* oh = g_w[mat][l][0];
    __nv_bfloat16* ol = g_w[mat][l][1];
    #pragma unroll
    for (int i = 0; i < 4; i++) {
        int nl = ty + i * 8;
        int n  = n0 + nl;
        int np = 4 * (n & 1023) + (n >> 10);
        float v = t[tx][nl];
        __nv_bfloat16 h = __float2bfloat16(v);
        oh[(size_t)np * HID + k0 + tx] = h;
        ol[(size_t)np * HID + k0 + tx] = __float2bfloat16(v - __bfloat162float(h));
    }
}

__global__ void xsplit_kernel(const float* __restrict__ x) {
    int i = blockIdx.x * blockDim.x + threadIdx.x;
    if (i >= T_STEPS * BH) return;
    float v = x[i];
    __nv_bfloat16 h = __float2bfloat16(v);
    g_xh[i] = h;
    g_xl[i] = __float2bfloat16(v - __bfloat162float(h));
}

// ---------------- persistent fused LSTM: all 120 steps in one launch ----------------
__global__ __launch_bounds__(256, 1) void lstm_persistent_kernel(float* __restrict__ out)
{
    extern __shared__ char smem[];
    __shared__ const __nv_bfloat16* sAp[6];
    __shared__ const __nv_bfloat16* sBp[6];

    const uint32_t sb = smem_u32(smem);
    const int tid  = threadIdx.x;
    const int lane = tid & 31;
    const int wid  = tid >> 5;
    const int wm = wid >> 2;           // 0..1
    const int wn = wid & 3;            // 0..3
    const int blockN   = blockIdx.x * 128;
    const int blockRow = blockIdx.y * 64;

    // per-thread cp.async load maps (A: 2, B: 4 cp16 per chunk)
    const int ld_row = tid >> 3;           // 0..31
    const int ld_c16 = tid & 7;            // 0..7
    uint32_t aDst[2], bDst[4];
    int aRow[2], bRow[4];
    #pragma unroll
    for (int r = 0; r < 2; r++) {
        int row = ld_row + r * 32;
        aRow[r] = row;
        aDst[r] = sw128((uint32_t)(row * 128 + ld_c16 * 16));
    }
    #pragma unroll
    for (int r = 0; r < 4; r++) {
        int row = ld_row + r * 32;
        bRow[r] = row;
        bDst[r] = A_BYTES + sw128((uint32_t)(row * 128 + ld_c16 * 16));
    }

    // ldmatrix offsets (relative to stage base)
    uint32_t aOff[2][4], bOff[2][4];
    {
        int mA = wm * 32 + (lane & 7) + ((lane >> 3) & 1) * 8;
        int kA = (lane >> 4) * 16;                  // bytes
        int nB = wn * 32 + (lane & 7) + ((lane >> 4) & 1) * 8;
        int kB = ((lane >> 3) & 1) * 16;
        #pragma unroll
        for (int ks = 0; ks < 4; ks++) {
            #pragma unroll
            for (int mi = 0; mi < 2; mi++)
                aOff[mi][ks] = sw128((uint32_t)((mA + mi * 16) * 128 + ks * 32 + kA));
            #pragma unroll
            for (int nh2 = 0; nh2 < 2; nh2++)
                bOff[nh2][ks] = A_BYTES + sw128((uint32_t)((nB + nh2 * 16) * 128 + ks * 32 + kB));
        }
    }

    #pragma unroll 1
    for (int step = 0; step < NSTEPS; step++) {
        const int t = step >> 2;
        const int j = step & 3;

        if (tid == 0) {
            const __nv_bfloat16* ah = (j == 0) ? g_xh + (size_t)t * BH : g_curh[j & 1];
            const __nv_bfloat16* al = (j == 0) ? g_xl + (size_t)t * BH : g_curl[j & 1];
            const __nv_bfloat16* hhp = g_hh[j][t & 1];
            const __nv_bfloat16* hlp = g_hl[j][t & 1];
            sAp[0] = ah;  sAp[1] = ah;  sAp[2] = al;
            sAp[3] = hhp; sAp[4] = hhp; sAp[5] = hlp;
            sBp[0] = g_w[0][j][0]; sBp[1] = g_w[0][j][1]; sBp[2] = g_w[0][j][0];
            sBp[3] = g_w[1][j][0]; sBp[4] = g_w[1][j][1]; sBp[5] = g_w[1][j][0];
        }
        __syncthreads();

        auto load_chunk = [&](int jc, int s) {
            int p   = jc >> 4;
            int kc0 = (jc & 15) * KC;
            const __nv_bfloat16* As = sAp[p];
            const __nv_bfloat16* Bs = sBp[p];
            uint32_t base = sb + (uint32_t)s * STAGE_BYTES;
            #pragma unroll
            for (int r = 0; r < 2; r++)
                cp16(base + aDst[r], As + (size_t)(blockRow + aRow[r]) * HID + kc0 + ld_c16 * 8);
            #pragma unroll
            for (int r = 0; r < 4; r++)
                cp16(base + bDst[r], Bs + (size_t)(blockN + bRow[r]) * HID + kc0 + ld_c16 * 8);
        };

        float d[2][4][4];
        #pragma unroll
        for (int mi = 0; mi < 2; mi++)
            #pragma unroll
            for (int ni = 0; ni < 4; ni++)
                #pragma unroll
                for (int r = 0; r < 4; r++) d[mi][ni][r] = 0.0f;

        load_chunk(0, 0);
        asm volatile("cp.async.commit_group;" ::: "memory");
        load_chunk(1, 1);
        asm volatile("cp.async.commit_group;" ::: "memory");

        int s_cmp = 0, s_load = 2;
        #pragma unroll 1
        for (int i = 0; i < NCHUNK; i++) {
            asm volatile("cp.async.wait_group 1;" ::: "memory");
            __syncthreads();
            if (i + 2 < NCHUNK) load_chunk(i + 2, s_load);
            asm volatile("cp.async.commit_group;" ::: "memory");

            uint32_t base = sb + (uint32_t)s_cmp * STAGE_BYTES;
            #pragma unroll
            for (int ks = 0; ks < 4; ks++) {
                uint32_t a[2][4], bt[2][4];
                #pragma unroll
                for (int mi = 0; mi < 2; mi++)
                    ldmat4(base + aOff[mi][ks], a[mi][0], a[mi][1], a[mi][2], a[mi][3]);
                #pragma unroll
                for (int nh2 = 0; nh2 < 2; nh2++)
                    ldmat4(base + bOff[nh2][ks], bt[nh2][0], bt[nh2][1], bt[nh2][2], bt[nh2][3]);
                #pragma unroll
                for (int mi = 0; mi < 2; mi++)
                    #pragma unroll
                    for (int ni = 0; ni < 4; ni++)
                        mma_bf16(d[mi][ni][0], d[mi][ni][1], d[mi][ni][2], d[mi][ni][3],
                                 a[mi][0], a[mi][1], a[mi][2], a[mi][3],
                                 bt[ni >> 1][(ni & 1) * 2], bt[ni >> 1][(ni & 1) * 2 + 1]);
            }
            if (++s_cmp == STAGES) s_cmp = 0;
            if (++s_load == STAGES) s_load = 0;
        }

        asm volatile("cp.async.wait_group 0;" ::: "memory");
        __syncthreads();   // smem now free for epilogue staging

        // stage accumulators: per-warp [32 rows][33 floats]
        float* st = (float*)(smem + (size_t)wid * 32 * 33 * 4);
        #pragma unroll
        for (int mi = 0; mi < 2; mi++) {
            int r0 = mi * 16 + (lane >> 2);
            #pragma unroll
            for (int ni = 0; ni < 4; ni++) {
                int c0 = ni * 8 + 2 * (lane & 3);
                st[r0 * 33 + c0]           = d[mi][ni][0];
                st[r0 * 33 + c0 + 1]       = d[mi][ni][1];
                st[(r0 + 8) * 33 + c0]     = d[mi][ni][2];
                st[(r0 + 8) * 33 + c0 + 1] = d[mi][ni][3];
            }
        }
        __syncwarp();

        // gate math: lane -> one batch row, 8 hidden units
        {
            const float* zrow = st + lane * 33;
            const int m  = blockRow + wm * 32 + lane;
            const int ug = (blockN >> 2) + wn * 8;
            const float4* bq = (const float4*)(&g_biasp[j][blockN + wn * 32]);
            float* cp = &g_c[j][(size_t)m * HID + ug];
            float4 co0 = *(const float4*)(cp);
            float4 co1 = *(const float4*)(cp + 4);
            float cold[8] = {co0.x, co0.y, co0.z, co0.w, co1.x, co1.y, co1.z, co1.w};
            float cn[8], hn[8];
            #pragma unroll
            for (int k = 0; k < 8; k++) {
                float4 bb = bq[k];
                float zi = zrow[4 * k]     + bb.x;
                float zf = zrow[4 * k + 1] + bb.y;
                float zg = zrow[4 * k + 2] + bb.z;
                float zo = zrow[4 * k + 3] + bb.w;
                float ig = 1.0f / (1.0f + __expf(-zi));
                float fg = 1.0f / (1.0f + __expf(-zf));
                float gg = tanhf(zg);
                float og = 1.0f / (1.0f + __expf(-zo));
                float c_ = fg * cold[k] + ig * gg;
                cn[k] = c_;
                hn[k] = og * tanhf(c_);
            }
            *(float4*)(cp)     = make_float4(cn[0], cn[1], cn[2], cn[3]);
            *(float4*)(cp + 4) = make_float4(cn[4], cn[5], cn[6], cn[7]);

            uint32_t chi[8], clo[8], hhi[8], hlo[8];
            #pragma unroll
            for (int k = 0; k < 8; k++) {
                split_bf(cn[k], chi[k], clo[k]);
                split_bf(hn[k], hhi[k], hlo[k]);
            }
            size_t so = (size_t)m * HID + ug;
            __nv_bfloat16* curh_o = g_curh[(j + 1) & 1];
            __nv_bfloat16* curl_o = g_curl[(j + 1) & 1];
            __nv_bfloat16* hh_o   = g_hh[j][(t + 1) & 1];
            __nv_bfloat16* hl_o   = g_hl[j][(t + 1) & 1];
            uint4 v;
            v = make_uint4(chi[0] | (chi[1] << 16), chi[2] | (chi[3] << 16),
                           chi[4] | (chi[5] << 16), chi[6] | (chi[7] << 16));
            *(uint4*)(curh_o + so) = v;
            v = make_uint4(clo[0] | (clo[1] << 16), clo[2] | (clo[3] << 16),
                           clo[4] | (clo[5] << 16), clo[6] | (clo[7] << 16));
            *(uint4*)(curl_o + so) = v;
            v = make_uint4(hhi[0] | (hhi[1] << 16), hhi[2] | (hhi[3] << 16),
                           hhi[4] | (hhi[5] << 16), hhi[6] | (hhi[7] << 16));
            *(uint4*)(hh_o + so) = v;
            v = make_uint4(hlo[0] | (hlo[1] << 16), hlo[2] | (hlo[3] << 16),
                           hlo[4] | (hlo[5] << 16), hlo[6] | (hlo[7] << 16));
            *(uint4*)(hl_o + so) = v;

            if (step == NSTEPS - 1) {
                *(float4*)(out + so)     = make_float4(cn[0], cn[1], cn[2], cn[3]);
                *(float4*)(out + so + 4) = make_float4(cn[4], cn[5], cn[6], cn[7]);
            }
        }

        // -------- grid-wide barrier (all 128 CTAs resident) --------
        if (step < NSTEPS - 1) {
            __syncthreads();
            if (tid == 0) {
                __threadfence();
                unsigned target = (unsigned)(step + 1) * GRID_CTAS;
                atomicAdd(&g_bar, 1u);
                while (atomicAdd(&g_bar, 0u) < target) __nanosleep(64);
            }
            __syncthreads();
        }
    }
}

// ---------------- host launcher ----------------
extern "C" void kernel_launch(void* const* d_in, const int* in_sizes, int n_in,
                              void* d_out, int out_size)
{
    const float* inputs = (const float*)d_in[0];
    const float* kernel = (const float*)d_in[1];
    const float* rec    = (const float*)d_in[2];
    const float* bias   = (const float*)d_in[3];
    float* out = (float*)d_out;

    cudaFuncSetAttribute(lstm_persistent_kernel,
                         cudaFuncAttributeMaxDynamicSharedMemorySize, SMEM_BYTES);

    {
        int n = LAYERS * BH;
        zero_state_kernel<<<(n + 255) / 256, 256>>>();
        bias_perm_kernel<<<(LAYERS * ZCOLS + 255) / 256, 256>>>(bias);
        wsplit_kernel<<<dim3(ZCOLS / 32, HID / 32, 2 * LAYERS), dim3(32, 8)>>>(kernel, rec);
        xsplit_kernel<<<(T_STEPS * BH + 255) / 256, 256>>>(inputs);
    }

    dim3 grid(32, 4);   // 128 CTAs — all resident (<=148 SMs), required by the barrier
    lstm_persistent_kernel<<<grid, 256, SMEM_BYTES>>>(out);
}

// round 9
// speedup vs baseline: 4.7827x; 1.2598x over previous
#include <cuda_runtime.h>
#include <cuda_bf16.h>
#include <cstdint>

#define T_STEPS 30
#define HID     1024
#define LAYERS  4
#define ZCOLS   4096
#define BH      (256 * HID)
#define NSTEPS  (T_STEPS * LAYERS)   // 120

#define KC          128               // bf16 k-elements per stage (2 SW128 panels)
#define NCHUNK      48                // 6 terms * (1024/128)
#define A_BYTES     16384             // 2 panels x (64 x 128B)
#define B_BYTES     32768             // 2 panels x (128 x 128B)
#define A_PANEL     8192
#define B_PANEL     16384
#define STAGE_BYTES (A_BYTES + B_BYTES)          // 49152
#define SMEM_BYTES  (3 * STAGE_BYTES)            // 147456
#define GRID_CTAS   128

// ---------------- scratch (__device__ globals) ----------------
__device__ __nv_bfloat16 g_w[2][LAYERS][2][ZCOLS * HID];
__device__ __nv_bfloat16 g_xh[T_STEPS * BH];
__device__ __nv_bfloat16 g_xl[T_STEPS * BH];
__device__ float         g_c[LAYERS][BH];
__device__ __nv_bfloat16 g_hh[LAYERS][2][BH];
__device__ __nv_bfloat16 g_hl[LAYERS][2][BH];
__device__ __nv_bfloat16 g_curh[2][BH];
__device__ __nv_bfloat16 g_curl[2][BH];
__device__ float         g_biasp[LAYERS][ZCOLS];
__device__ unsigned      g_bar;

// ---------------- helpers ----------------
__device__ __forceinline__ uint32_t smem_u32(const void* p) {
    uint32_t a;
    asm("{ .reg .u64 t; cvta.to.shared.u64 t, %1; cvt.u32.u64 %0, t; }" : "=r"(a) : "l"(p));
    return a;
}
__device__ __forceinline__ void cp16(uint32_t dst, const void* src) {
    asm volatile("cp.async.cg.shared.global [%0], [%1], 16;"
                 :: "r"(dst), "l"(__cvta_generic_to_global(src)) : "memory");
}
__device__ __forceinline__ uint32_t sw128(uint32_t off) {
    return off ^ ((off >> 3) & 0x70);
}
__device__ __forceinline__ void ldmat4(uint32_t addr, uint32_t& r0, uint32_t& r1,
                                       uint32_t& r2, uint32_t& r3) {
    asm volatile("ldmatrix.sync.aligned.m8n8.x4.shared.b16 {%0,%1,%2,%3}, [%4];"
                 : "=r"(r0), "=r"(r1), "=r"(r2), "=r"(r3) : "r"(addr));
}
__device__ __forceinline__ void mma_bf16(float& d0, float& d1, float& d2, float& d3,
                                         uint32_t a0, uint32_t a1, uint32_t a2, uint32_t a3,
                                         uint32_t b0, uint32_t b1) {
    asm volatile("mma.sync.aligned.m16n8k16.row.col.f32.bf16.bf16.f32 "
                 "{%0,%1,%2,%3},{%4,%5,%6,%7},{%8,%9},{%0,%1,%2,%3};"
                 : "+f"(d0), "+f"(d1), "+f"(d2), "+f"(d3)
                 : "r"(a0), "r"(a1), "r"(a2), "r"(a3), "r"(b0), "r"(b1));
}
__device__ __forceinline__ void split_bf(float x, uint32_t& hi, uint32_t& lo) {
    __nv_bfloat16 h = __float2bfloat16(x);
    __nv_bfloat16 l = __float2bfloat16(x - __bfloat162float(h));
    hi = (uint32_t)__bfloat16_as_ushort(h);
    lo = (uint32_t)__bfloat16_as_ushort(l);
}

struct Ptrs {
    const __nv_bfloat16 *ah, *al, *hhp, *hlp, *w1h, *w1l, *w2h, *w2l;
};
__device__ __forceinline__ void get_ptrs(int step, Ptrs& P) {
    int t = step >> 2, j = step & 3;
    P.ah  = (j == 0) ? g_xh + (size_t)t * BH : g_curh[j & 1];
    P.al  = (j == 0) ? g_xl + (size_t)t * BH : g_curl[j & 1];
    P.hhp = g_hh[j][t & 1];
    P.hlp = g_hl[j][t & 1];
    P.w1h = g_w[0][j][0]; P.w1l = g_w[0][j][1];
    P.w2h = g_w[1][j][0]; P.w2l = g_w[1][j][1];
}
__device__ __forceinline__ const __nv_bfloat16* selA(const Ptrs& P, int p) {
    return (p <= 1) ? P.ah : (p == 2) ? P.al : (p <= 4) ? P.hhp : P.hlp;
}
__device__ __forceinline__ const __nv_bfloat16* selB(const Ptrs& P, int p) {
    return (p == 0 || p == 2) ? P.w1h : (p == 1) ? P.w1l : (p == 4) ? P.w2l : P.w2h;
}

// ---------------- init kernels ----------------
__global__ void zero_state_kernel() {
    int i = blockIdx.x * blockDim.x + threadIdx.x;
    if (i == 0) g_bar = 0u;
    int nc = LAYERS * BH;
    int nh = LAYERS * 2 * BH / 2;
    if (i < nc) ((float*)g_c)[i] = 0.0f;
    if (i < nh) { ((uint32_t*)g_hh)[i] = 0u; ((uint32_t*)g_hl)[i] = 0u; }
}

__global__ void bias_perm_kernel(const float* __restrict__ bias) {
    int i = blockIdx.x * blockDim.x + threadIdx.x;
    if (i >= LAYERS * ZCOLS) return;
    int l = i >> 12, n = i & 4095;
    int np = 4 * (n & 1023) + (n >> 10);
    g_biasp[l][np] = bias[i];
}

__global__ void wsplit_kernel(const float* __restrict__ kern, const float* __restrict__ rec) {
    __shared__ float t[32][33];
    int mat = blockIdx.z >> 2;
    int l   = blockIdx.z & 3;
    const float* src = (mat ? rec : kern) + (size_t)l * HID * ZCOLS;
    int n0 = blockIdx.x * 32, k0 = blockIdx.y * 32;
    int tx = threadIdx.x, ty = threadIdx.y;
    #pragma unroll
    for (int i = 0; i < 4; i++)
        t[ty + i * 8][tx] = src[(size_t)(k0 + ty + i * 8) * ZCOLS + n0 + tx];
    __syncthreads();
    __nv_bfloat16* oh = g_w[mat][l][0];
    __nv_bfloat16* ol = g_w[mat][l][1];
    #pragma unroll
    for (int i = 0; i < 4; i++) {
        int nl = ty + i * 8;
        int n  = n0 + nl;
        int np = 4 * (n & 1023) + (n >> 10);
        float v = t[tx][nl];
        __nv_bfloat16 h = __float2bfloat16(v);
        oh[(size_t)np * HID + k0 + tx] = h;
        ol[(size_t)np * HID + k0 + tx] = __float2bfloat16(v - __bfloat162float(h));
    }
}

__global__ void xsplit_kernel(const float* __restrict__ x) {
    int i = blockIdx.x * blockDim.x + threadIdx.x;
    if (i >= T_STEPS * BH) return;
    float v = x[i];
    __nv_bfloat16 h = __float2bfloat16(v);
    g_xh[i] = h;
    g_xl[i] = __float2bfloat16(v - __bfloat162float(h));
}

// ---------------- persistent fused LSTM ----------------
__global__ __launch_bounds__(256, 1) void lstm_persistent_kernel(float* __restrict__ out)
{
    extern __shared__ char smem[];
    const uint32_t sb = smem_u32(smem);
    const int tid  = threadIdx.x;
    const int lane = tid & 31;
    const int wid  = tid >> 5;
    const int wm = wid >> 2;
    const int wn = wid & 3;
    const int blockN   = blockIdx.x * 128;
    const int blockRow = blockIdx.y * 64;

    // cp.async load maps
    const int ld_row = tid >> 3;           // 0..31
    const int ld_c16 = tid & 7;            // 0..7
    uint32_t aDst[2], bDst[4];
    #pragma unroll
    for (int r = 0; r < 2; r++)
        aDst[r] = sw128((uint32_t)((ld_row + r * 32) * 128 + ld_c16 * 16));
    #pragma unroll
    for (int r = 0; r < 4; r++)
        bDst[r] = A_BYTES + sw128((uint32_t)((ld_row + r * 32) * 128 + ld_c16 * 16));

    // ldmatrix base offsets (XOR (ks&3)*32; panel offset added at use)
    uint32_t aBase[2], bBase[2];
    {
        int mA = wm * 32 + (lane & 7) + ((lane >> 3) & 1) * 8;
        int kA = (lane >> 4) * 16;
        int nB = wn * 32 + (lane & 7) + ((lane >> 4) & 1) * 8;
        int kB = ((lane >> 3) & 1) * 16;
        #pragma unroll
        for (int mi = 0; mi < 2; mi++) {
            int row = mA + mi * 16;
            aBase[mi] = (uint32_t)(row * 128) + ((uint32_t)kA ^ ((uint32_t)(row & 7) * 16));
        }
        #pragma unroll
        for (int nh2 = 0; nh2 < 2; nh2++) {
            int row = nB + nh2 * 16;
            bBase[nh2] = A_BYTES + (uint32_t)(row * 128) + ((uint32_t)kB ^ ((uint32_t)(row & 7) * 16));
        }
    }

    auto loadA = [&](const Ptrs& P, int jc, int s) {
        int p = jc >> 3, k0 = (jc & 7) * KC;
        const __nv_bfloat16* As = selA(P, p);
        uint32_t base = sb + (uint32_t)s * STAGE_BYTES;
        #pragma unroll
        for (int pi = 0; pi < 2; pi++)
            #pragma unroll
            for (int r = 0; r < 2; r++)
                cp16(base + pi * A_PANEL + aDst[r],
                     As + (size_t)(blockRow + ld_row + r * 32) * HID + k0 + pi * 64 + ld_c16 * 8);
    };
    auto loadB = [&](const Ptrs& P, int jc, int s) {
        int p = jc >> 3, k0 = (jc & 7) * KC;
        const __nv_bfloat16* Bs = selB(P, p);
        uint32_t base = sb + (uint32_t)s * STAGE_BYTES;
        #pragma unroll
        for (int pi = 0; pi < 2; pi++)
            #pragma unroll
            for (int r = 0; r < 4; r++)
                cp16(base + pi * B_PANEL + bDst[r],
                     Bs + (size_t)(blockN + ld_row + r * 32) * HID + k0 + pi * 64 + ld_c16 * 8);
    };

    auto ldsm_ks = [&](uint32_t base, int ks, uint32_t a[2][4], uint32_t bt[2][4]) {
        uint32_t xk  = (uint32_t)((ks & 3) * 32);
        uint32_t pkA = (uint32_t)((ks >> 2) * A_PANEL);
        uint32_t pkB = (uint32_t)((ks >> 2) * B_PANEL);
        #pragma unroll
        for (int mi = 0; mi < 2; mi++)
            ldmat4(base + pkA + (aBase[mi] ^ xk), a[mi][0], a[mi][1], a[mi][2], a[mi][3]);
        #pragma unroll
        for (int nh2 = 0; nh2 < 2; nh2++)
            ldmat4(base + pkB + (bBase[nh2] ^ xk), bt[nh2][0], bt[nh2][1], bt[nh2][2], bt[nh2][3]);
    };

    // prologue: prefetch chunks 0,1 (B first — matches in-loop group order)
    Ptrs P;
    get_ptrs(0, P);
    loadB(P, 0, 0); asm volatile("cp.async.commit_group;" ::: "memory");
    loadB(P, 1, 1); asm volatile("cp.async.commit_group;" ::: "memory");
    loadA(P, 0, 0); asm volatile("cp.async.commit_group;" ::: "memory");
    loadA(P, 1, 1); asm volatile("cp.async.commit_group;" ::: "memory");

    #pragma unroll 1
    for (int step = 0; step < NSTEPS; step++) {
        const int t = step >> 2;
        const int j = step & 3;
        get_ptrs(step, P);

        float d[2][4][4];
        #pragma unroll
        for (int mi = 0; mi < 2; mi++)
            #pragma unroll
            for (int ni = 0; ni < 4; ni++)
                #pragma unroll
                for (int r = 0; r < 4; r++) d[mi][ni][r] = 0.0f;

        int s_cmp = 0, s_load = 2;
        #pragma unroll 1
        for (int i = 0; i < NCHUNK; i++) {
            asm volatile("cp.async.wait_group 1;" ::: "memory");
            __syncthreads();
            if (i + 2 < NCHUNK) { loadA(P, i + 2, s_load); loadB(P, i + 2, s_load); }
            asm volatile("cp.async.commit_group;" ::: "memory");

            uint32_t base = sb + (uint32_t)s_cmp * STAGE_BYTES;
            uint32_t a[2][2][4], bt[2][2][4];
            ldsm_ks(base, 0, a[0], bt[0]);
            #pragma unroll
            for (int ks = 0; ks < 8; ks++) {
                int cur = ks & 1;
                if (ks < 7) ldsm_ks(base, ks + 1, a[cur ^ 1], bt[cur ^ 1]);
                #pragma unroll
                for (int mi = 0; mi < 2; mi++)
                    #pragma unroll
                    for (int ni = 0; ni < 4; ni++)
                        mma_bf16(d[mi][ni][0], d[mi][ni][1], d[mi][ni][2], d[mi][ni][3],
                                 a[cur][mi][0], a[cur][mi][1], a[cur][mi][2], a[cur][mi][3],
                                 bt[cur][ni >> 1][(ni & 1) * 2], bt[cur][ni >> 1][(ni & 1) * 2 + 1]);
            }
            if (++s_cmp == 3) s_cmp = 0;
            if (++s_load == 3) s_load = 0;
        }

        asm volatile("cp.async.wait_group 0;" ::: "memory");
        __syncthreads();

        // stage accumulators: per-warp [32 rows][33 floats]
        float* st = (float*)(smem + (size_t)wid * 32 * 33 * 4);
        #pragma unroll
        for (int mi = 0; mi < 2; mi++) {
            int r0 = mi * 16 + (lane >> 2);
            #pragma unroll
            for (int ni = 0; ni < 4; ni++) {
                int c0 = ni * 8 + 2 * (lane & 3);
                st[r0 * 33 + c0]           = d[mi][ni][0];
                st[r0 * 33 + c0 + 1]       = d[mi][ni][1];
                st[(r0 + 8) * 33 + c0]     = d[mi][ni][2];
                st[(r0 + 8) * 33 + c0 + 1] = d[mi][ni][3];
            }
        }
        __syncwarp();

        // gate math
        {
            const float* zrow = st + lane * 33;
            const int m  = blockRow + wm * 32 + lane;
            const int ug = (blockN >> 2) + wn * 8;
            const float4* bq = (const float4*)(&g_biasp[j][blockN + wn * 32]);
            float* cp = &g_c[j][(size_t)m * HID + ug];
            float4 co0 = *(const float4*)(cp);
            float4 co1 = *(const float4*)(cp + 4);
            float cold[8] = {co0.x, co0.y, co0.z, co0.w, co1.x, co1.y, co1.z, co1.w};
            float cn[8], hn[8];
            #pragma unroll
            for (int k = 0; k < 8; k++) {
                float4 bb = bq[k];
                float zi = zrow[4 * k]     + bb.x;
                float zf = zrow[4 * k + 1] + bb.y;
                float zg = zrow[4 * k + 2] + bb.z;
                float zo = zrow[4 * k + 3] + bb.w;
                float ig = 1.0f / (1.0f + __expf(-zi));
                float fg = 1.0f / (1.0f + __expf(-zf));
                float gg = tanhf(zg);
                float og = 1.0f / (1.0f + __expf(-zo));
                float c_ = fg * cold[k] + ig * gg;
                cn[k] = c_;
                hn[k] = og * tanhf(c_);
            }
            *(float4*)(cp)     = make_float4(cn[0], cn[1], cn[2], cn[3]);
            *(float4*)(cp + 4) = make_float4(cn[4], cn[5], cn[6], cn[7]);

            uint32_t chi[8], clo[8], hhi[8], hlo[8];
            #pragma unroll
            for (int k = 0; k < 8; k++) {
                split_bf(cn[k], chi[k], clo[k]);
                split_bf(hn[k], hhi[k], hlo[k]);
            }
            size_t so = (size_t)m * HID + ug;
            __nv_bfloat16* curh_o = g_curh[(j + 1) & 1];
            __nv_bfloat16* curl_o = g_curl[(j + 1) & 1];
            __nv_bfloat16* hh_o   = g_hh[j][(t + 1) & 1];
            __nv_bfloat16* hl_o   = g_hl[j][(t + 1) & 1];
            uint4 v;
            v = make_uint4(chi[0] | (chi[1] << 16), chi[2] | (chi[3] << 16),
                           chi[4] | (chi[5] << 16), chi[6] | (chi[7] << 16));
            *(uint4*)(curh_o + so) = v;
            v = make_uint4(clo[0] | (clo[1] << 16), clo[2] | (clo[3] << 16),
                           clo[4] | (clo[5] << 16), clo[6] | (clo[7] << 16));
            *(uint4*)(curl_o + so) = v;
            v = make_uint4(hhi[0] | (hhi[1] << 16), hhi[2] | (hhi[3] << 16),
                           hhi[4] | (hhi[5] << 16), hhi[6] | (hhi[7] << 16));
            *(uint4*)(hh_o + so) = v;
            v = make_uint4(hlo[0] | (hlo[1] << 16), hlo[2] | (hlo[3] << 16),
                           hlo[4] | (hlo[5] << 16), hlo[6] | (hlo[7] << 16));
            *(uint4*)(hl_o + so) = v;

            if (step == NSTEPS - 1) {
                *(float4*)(out + so)     = make_float4(cn[0], cn[1], cn[2], cn[3]);
                *(float4*)(out + so + 4) = make_float4(cn[4], cn[5], cn[6], cn[7]);
            }
        }

        // -------- barrier + cross-step prefetch --------
        if (step < NSTEPS - 1) {
            __syncthreads();   // epilogue smem reads done before prefetch overwrites stages
            Ptrs Pn;
            get_ptrs(step + 1, Pn);
            // weights are state-independent: prefetch BEFORE the barrier
            loadB(Pn, 0, 0); asm volatile("cp.async.commit_group;" ::: "memory");
            loadB(Pn, 1, 1); asm volatile("cp.async.commit_group;" ::: "memory");
            if (tid == 0) {
                __threadfence();
                atomicAdd(&g_bar, 1u);
                unsigned target = (unsigned)(step + 1) * GRID_CTAS;
                unsigned v;
                do {
                    asm volatile("ld.acquire.gpu.global.u32 %0, [%1];" : "=r"(v) : "l"(&g_bar));
                } while (v < target);
            }
            __syncthreads();
            // activations depend on the step we just synced on
            loadA(Pn, 0, 0); asm volatile("cp.async.commit_group;" ::: "memory");
            loadA(Pn, 1, 1); asm volatile("cp.async.commit_group;" ::: "memory");
        }
    }
}

// ---------------- host launcher ----------------
extern "C" void kernel_launch(void* const* d_in, const int* in_sizes, int n_in,
                              void* d_out, int out_size)
{
    const float* inputs = (const float*)d_in[0];
    const float* kernel = (const float*)d_in[1];
    const float* rec    = (const float*)d_in[2];
    const float* bias   = (const float*)d_in[3];
    float* out = (float*)d_out;

    cudaFuncSetAttribute(lstm_persistent_kernel,
                         cudaFuncAttributeMaxDynamicSharedMemorySize, SMEM_BYTES);

    {
        int n = LAYERS * BH;
        zero_state_kernel<<<(n + 255) / 256, 256>>>();
        bias_perm_kernel<<<(LAYERS * ZCOLS + 255) / 256, 256>>>(bias);
        wsplit_kernel<<<dim3(ZCOLS / 32, HID / 32, 2 * LAYERS), dim3(32, 8)>>>(kernel, rec);
        xsplit_kernel<<<(T_STEPS * BH + 255) / 256, 256>>>(inputs);
    }

    dim3 grid(32, 4);   // 128 CTAs, all resident — required by the barrier
    lstm_persistent_kernel<<<grid, 256, SMEM_BYTES>>>(out);
}